// round 1
// baseline (speedup 1.0000x reference)
#include <cuda_runtime.h>
#include <math.h>
#include <stdint.h>

// Problem constants
#define SEQ     2048
#define HIDDEN  4096
#define NH      32
#define NKV     8
#define HD      128
#define QDIM    (NH*HD)    // 4096
#define KVDIM   (NKV*HD)   // 1024

// Scratch (device globals — no runtime allocation allowed)
__device__ float g_q[SEQ * QDIM];                     // 32 MB
__device__ float g_k[SEQ * KVDIM];                    // 8 MB
__device__ float g_v[SEQ * KVDIM];                    // 8 MB
__device__ float g_s[(size_t)NH * SEQ * SEQ];         // 512 MB
__device__ float g_attn[SEQ * QDIM];                  // 32 MB

// ---------------------------------------------------------------------------
// Generic NT SGEMM: C[M,N] = alpha * A[M,K] @ B[N,K]^T + bias
// 128x128 block tile, BK=16, 256 threads, 8x8 microtile (4+4 split rows/cols)
// Batched over blockIdx.z with per-z strides; B's z index is z / bzdiv.
// All of M%128, N%128, K%16 are 0 for every call in this problem.
// ---------------------------------------------------------------------------
__global__ __launch_bounds__(256) void gemm_nt_kernel(
    const float* __restrict__ A, int lda, long strideA,
    const float* __restrict__ B, int ldb, long strideB, int bzdiv,
    const float* __restrict__ bias,
    float* __restrict__ C, int ldc, long strideC,
    int M, int N, int K, float alpha)
{
    __shared__ float As[16][128];
    __shared__ float Bs[16][128];

    const int tid = threadIdx.x;
    const int bz  = blockIdx.z;
    A += (size_t)bz * strideA;
    B += (size_t)(bz / bzdiv) * strideB;
    C += (size_t)bz * strideC;

    const int bm = blockIdx.y * 128;
    const int bn = blockIdx.x * 128;

    const int tx = tid & 15;   // n-dir, 16
    const int ty = tid >> 4;   // m-dir, 16

    const int lrow = tid >> 2;          // 0..63
    const int lcol = (tid & 3) * 4;     // 0,4,8,12

    float acc[8][8];
    #pragma unroll
    for (int i = 0; i < 8; i++)
        #pragma unroll
        for (int j = 0; j < 8; j++) acc[i][j] = 0.f;

    for (int k0 = 0; k0 < K; k0 += 16) {
        float4 a0 = *(const float4*)(A + (size_t)(bm + lrow)      * lda + k0 + lcol);
        float4 a1 = *(const float4*)(A + (size_t)(bm + lrow + 64) * lda + k0 + lcol);
        float4 b0 = *(const float4*)(B + (size_t)(bn + lrow)      * ldb + k0 + lcol);
        float4 b1 = *(const float4*)(B + (size_t)(bn + lrow + 64) * ldb + k0 + lcol);
        __syncthreads();
        As[lcol+0][lrow]    = a0.x; As[lcol+1][lrow]    = a0.y;
        As[lcol+2][lrow]    = a0.z; As[lcol+3][lrow]    = a0.w;
        As[lcol+0][lrow+64] = a1.x; As[lcol+1][lrow+64] = a1.y;
        As[lcol+2][lrow+64] = a1.z; As[lcol+3][lrow+64] = a1.w;
        Bs[lcol+0][lrow]    = b0.x; Bs[lcol+1][lrow]    = b0.y;
        Bs[lcol+2][lrow]    = b0.z; Bs[lcol+3][lrow]    = b0.w;
        Bs[lcol+0][lrow+64] = b1.x; Bs[lcol+1][lrow+64] = b1.y;
        Bs[lcol+2][lrow+64] = b1.z; Bs[lcol+3][lrow+64] = b1.w;
        __syncthreads();

        #pragma unroll
        for (int kk = 0; kk < 16; kk++) {
            float4 av0 = *(const float4*)&As[kk][ty*4];
            float4 av1 = *(const float4*)&As[kk][ty*4 + 64];
            float4 bv0 = *(const float4*)&Bs[kk][tx*4];
            float4 bv1 = *(const float4*)&Bs[kk][tx*4 + 64];
            float a[8] = {av0.x,av0.y,av0.z,av0.w, av1.x,av1.y,av1.z,av1.w};
            float b[8] = {bv0.x,bv0.y,bv0.z,bv0.w, bv1.x,bv1.y,bv1.z,bv1.w};
            #pragma unroll
            for (int i = 0; i < 8; i++)
                #pragma unroll
                for (int j = 0; j < 8; j++)
                    acc[i][j] = fmaf(a[i], b[j], acc[i][j]);
        }
    }

    #pragma unroll
    for (int i = 0; i < 8; i++) {
        int m = bm + ty*4 + ((i & 4) ? 64 + (i & 3) : (i & 3));
        float* crow = C + (size_t)m * ldc + bn;
        #pragma unroll
        for (int jh = 0; jh < 2; jh++) {
            int nc = tx*4 + jh*64;
            float4 o;
            o.x = alpha*acc[i][jh*4+0] + (bias ? bias[bn+nc+0] : 0.f);
            o.y = alpha*acc[i][jh*4+1] + (bias ? bias[bn+nc+1] : 0.f);
            o.z = alpha*acc[i][jh*4+2] + (bias ? bias[bn+nc+2] : 0.f);
            o.w = alpha*acc[i][jh*4+3] + (bias ? bias[bn+nc+3] : 0.f);
            *(float4*)(crow + nc) = o;
        }
    }
}

// ---------------------------------------------------------------------------
// NN SGEMM: C[M,N] = alpha * A[M,K] @ B[K,N] (used for P @ V)
// Same tiling; only the B-tile load differs.
// ---------------------------------------------------------------------------
__global__ __launch_bounds__(256) void gemm_nn_kernel(
    const float* __restrict__ A, int lda, long strideA,
    const float* __restrict__ B, int ldb, long strideB, int bzdiv,
    float* __restrict__ C, int ldc, long strideC,
    int M, int N, int K, float alpha)
{
    __shared__ float As[16][128];
    __shared__ float Bs[16][128];

    const int tid = threadIdx.x;
    const int bz  = blockIdx.z;
    A += (size_t)bz * strideA;
    B += (size_t)(bz / bzdiv) * strideB;
    C += (size_t)bz * strideC;

    const int bm = blockIdx.y * 128;
    const int bn = blockIdx.x * 128;

    const int tx = tid & 15;
    const int ty = tid >> 4;

    const int lrow = tid >> 2;           // A loader: 0..63
    const int lcol = (tid & 3) * 4;
    const int bkr  = tid >> 5;           // B loader row: 0..7
    const int bnc  = (tid & 31) * 4;     // B loader col: 0..124

    float acc[8][8];
    #pragma unroll
    for (int i = 0; i < 8; i++)
        #pragma unroll
        for (int j = 0; j < 8; j++) acc[i][j] = 0.f;

    for (int k0 = 0; k0 < K; k0 += 16) {
        float4 a0 = *(const float4*)(A + (size_t)(bm + lrow)      * lda + k0 + lcol);
        float4 a1 = *(const float4*)(A + (size_t)(bm + lrow + 64) * lda + k0 + lcol);
        float4 b0 = *(const float4*)(B + (size_t)(k0 + bkr)     * ldb + bn + bnc);
        float4 b1 = *(const float4*)(B + (size_t)(k0 + bkr + 8) * ldb + bn + bnc);
        __syncthreads();
        As[lcol+0][lrow]    = a0.x; As[lcol+1][lrow]    = a0.y;
        As[lcol+2][lrow]    = a0.z; As[lcol+3][lrow]    = a0.w;
        As[lcol+0][lrow+64] = a1.x; As[lcol+1][lrow+64] = a1.y;
        As[lcol+2][lrow+64] = a1.z; As[lcol+3][lrow+64] = a1.w;
        *(float4*)&Bs[bkr][bnc]     = b0;
        *(float4*)&Bs[bkr+8][bnc]   = b1;
        __syncthreads();

        #pragma unroll
        for (int kk = 0; kk < 16; kk++) {
            float4 av0 = *(const float4*)&As[kk][ty*4];
            float4 av1 = *(const float4*)&As[kk][ty*4 + 64];
            float4 bv0 = *(const float4*)&Bs[kk][tx*4];
            float4 bv1 = *(const float4*)&Bs[kk][tx*4 + 64];
            float a[8] = {av0.x,av0.y,av0.z,av0.w, av1.x,av1.y,av1.z,av1.w};
            float b[8] = {bv0.x,bv0.y,bv0.z,bv0.w, bv1.x,bv1.y,bv1.z,bv1.w};
            #pragma unroll
            for (int i = 0; i < 8; i++)
                #pragma unroll
                for (int j = 0; j < 8; j++)
                    acc[i][j] = fmaf(a[i], b[j], acc[i][j]);
        }
    }

    #pragma unroll
    for (int i = 0; i < 8; i++) {
        int m = bm + ty*4 + ((i & 4) ? 64 + (i & 3) : (i & 3));
        float* crow = C + (size_t)m * ldc + bn;
        #pragma unroll
        for (int jh = 0; jh < 2; jh++) {
            int nc = tx*4 + jh*64;
            float4 o;
            o.x = alpha*acc[i][jh*4+0];
            o.y = alpha*acc[i][jh*4+1];
            o.z = alpha*acc[i][jh*4+2];
            o.w = alpha*acc[i][jh*4+3];
            *(float4*)(crow + nc) = o;
        }
    }
}

// ---------------------------------------------------------------------------
// RoPE in place: t is [seq, nheads*128]; pair (d, d+64) rotated by pos*inv_freq[d]
// ---------------------------------------------------------------------------
__global__ void rope_kernel(float* __restrict__ t,
                            const int* __restrict__ pos_ids,
                            int nheads)
{
    int idx = blockIdx.x * blockDim.x + threadIdx.x;
    int total = SEQ * nheads * 64;
    if (idx >= total) return;
    int d = idx & 63;
    int h = (idx >> 6) % nheads;
    int srow = idx / (64 * nheads);

    float pos = (float)pos_ids[srow];
    // inv_freq = BASE^(-(2d)/HD), match jax fp32 pipeline closely
    float inv = powf(10000.0f, -(float)(2*d) / 128.0f);
    float ang = pos * inv;
    float c = cosf(ang), s = sinf(ang);

    float* p = t + (size_t)srow * (nheads * HD) + h * HD;
    float lo = p[d], hi = p[d + 64];
    p[d]      = lo * c - hi * s;
    p[d + 64] = hi * c + lo * s;
}

// ---------------------------------------------------------------------------
// Row softmax over S: one block (256 thr) per row of 2048
// ---------------------------------------------------------------------------
__global__ __launch_bounds__(256) void softmax_kernel(float* __restrict__ S)
{
    const int n = SEQ;
    float* row = S + (size_t)blockIdx.x * n;
    int tid = threadIdx.x;
    int wid = tid >> 5, lid = tid & 31;
    __shared__ float red[8];

    float v[8];
    float m = -1e30f;
    #pragma unroll
    for (int i = 0; i < 8; i++) { v[i] = row[tid + i*256]; m = fmaxf(m, v[i]); }
    #pragma unroll
    for (int o = 16; o; o >>= 1) m = fmaxf(m, __shfl_xor_sync(0xffffffffu, m, o));
    if (lid == 0) red[wid] = m;
    __syncthreads();
    float bm = red[0];
    #pragma unroll
    for (int i = 1; i < 8; i++) bm = fmaxf(bm, red[i]);
    __syncthreads();

    float sum = 0.f;
    #pragma unroll
    for (int i = 0; i < 8; i++) { v[i] = expf(v[i] - bm); sum += v[i]; }
    #pragma unroll
    for (int o = 16; o; o >>= 1) sum += __shfl_xor_sync(0xffffffffu, sum, o);
    if (lid == 0) red[wid] = sum;
    __syncthreads();
    float tot = 0.f;
    #pragma unroll
    for (int i = 0; i < 8; i++) tot += red[i];
    float inv = 1.0f / tot;
    #pragma unroll
    for (int i = 0; i < 8; i++) row[tid + i*256] = v[i] * inv;
}

// ---------------------------------------------------------------------------
// Launch
// inputs: 0:x 1:position_ids 2:wq 3:bq 4:wk 5:bk 6:wv 7:bv 8:wo 9:bo
// ---------------------------------------------------------------------------
extern "C" void kernel_launch(void* const* d_in, const int* in_sizes, int n_in,
                              void* d_out, int out_size)
{
    const float* x   = (const float*)d_in[0];
    const int*   pid = (const int*)  d_in[1];
    const float* wq  = (const float*)d_in[2];
    const float* bq  = (const float*)d_in[3];
    const float* wk  = (const float*)d_in[4];
    const float* bk  = (const float*)d_in[5];
    const float* wv  = (const float*)d_in[6];
    const float* bv  = (const float*)d_in[7];
    const float* wo  = (const float*)d_in[8];
    const float* bo  = (const float*)d_in[9];
    float* out = (float*)d_out;

    float *q, *k, *v, *s, *attn;
    cudaGetSymbolAddress((void**)&q,    g_q);
    cudaGetSymbolAddress((void**)&k,    g_k);
    cudaGetSymbolAddress((void**)&v,    g_v);
    cudaGetSymbolAddress((void**)&s,    g_s);
    cudaGetSymbolAddress((void**)&attn, g_attn);

    dim3 thr(256);

    // 1. Q/K/V projections (NT):  q = x @ wq^T + bq  etc.
    gemm_nt_kernel<<<dim3(QDIM/128,  SEQ/128, 1), thr>>>(
        x, HIDDEN, 0, wq, HIDDEN, 0, 1, bq, q, QDIM, 0, SEQ, QDIM, HIDDEN, 1.0f);
    gemm_nt_kernel<<<dim3(KVDIM/128, SEQ/128, 1), thr>>>(
        x, HIDDEN, 0, wk, HIDDEN, 0, 1, bk, k, KVDIM, 0, SEQ, KVDIM, HIDDEN, 1.0f);
    gemm_nt_kernel<<<dim3(KVDIM/128, SEQ/128, 1), thr>>>(
        x, HIDDEN, 0, wv, HIDDEN, 0, 1, bv, v, KVDIM, 0, SEQ, KVDIM, HIDDEN, 1.0f);

    // 2. RoPE on q (32 heads) and k (8 heads)
    {
        int tq = SEQ * NH  * 64;
        int tk = SEQ * NKV * 64;
        rope_kernel<<<(tq + 255)/256, 256>>>(q, pid, NH);
        rope_kernel<<<(tk + 255)/256, 256>>>(k, pid, NKV);
    }

    // 3. Scores: S[h] = (Q_h @ K_{h/4}^T) / sqrt(128)   (NT, batched over 32 heads)
    const float inv_sqrt_d = 0.08838834764831845f; // 1/sqrt(128)
    gemm_nt_kernel<<<dim3(SEQ/128, SEQ/128, NH), thr>>>(
        q, QDIM, HD,             // A: per-head column offset 128
        k, KVDIM, HD, 4,         // B: kv head = h/4
        nullptr,
        s, SEQ, (long)SEQ*SEQ,   // C: per-head 2048x2048
        SEQ, SEQ, HD, inv_sqrt_d);

    // 4. Softmax over each of 32*2048 rows
    softmax_kernel<<<NH * SEQ, 256>>>(s);

    // 5. attn[h] = P_h @ V_{h/4}   (NN, batched)
    gemm_nn_kernel<<<dim3(HD/128, SEQ/128, NH), thr>>>(
        s, SEQ, (long)SEQ*SEQ,
        v, KVDIM, HD, 4,
        attn, QDIM, HD,
        SEQ, HD, SEQ, 1.0f);

    // 6. Output projection: out = attn @ wo^T + bo  (NT)
    gemm_nt_kernel<<<dim3(HIDDEN/128, SEQ/128, 1), thr>>>(
        attn, QDIM, 0, wo, QDIM, 0, 1, bo, out, HIDDEN, 0, SEQ, HIDDEN, QDIM, 1.0f);
}

// round 9
// speedup vs baseline: 2.5138x; 2.5138x over previous
#include <cuda_runtime.h>
#include <math.h>
#include <stdint.h>

// Problem constants
#define SEQ     2048
#define HIDDEN  4096
#define NH      32
#define NKV     8
#define HD      128
#define QDIM    (NH*HD)    // 4096
#define KVDIM   (NKV*HD)   // 1024

// Scratch (device globals — no runtime allocation allowed)
__device__ float g_q[SEQ * QDIM];                     // 32 MB
__device__ float g_k[SEQ * KVDIM];                    // 8 MB
__device__ float g_vt[KVDIM * SEQ];                   // 8 MB (V transposed: [1024][2048])
__device__ float g_s[(size_t)NH * SEQ * SEQ];         // 512 MB
__device__ float g_attn[SEQ * QDIM];                  // 32 MB

// ---------------------------------------------------------------------------
// TF32 helpers
// ---------------------------------------------------------------------------
__device__ __forceinline__ uint32_t f2t(float f) {
    uint32_t u;
    asm("cvt.rna.tf32.f32 %0, %1;" : "=r"(u) : "f"(f));
    return u;
}

__device__ __forceinline__ void mma_tf32(float* c, const uint32_t* a, const uint32_t* b) {
    asm volatile(
        "mma.sync.aligned.m16n8k8.row.col.f32.tf32.tf32.f32 "
        "{%0,%1,%2,%3},{%4,%5,%6,%7},{%8,%9},{%0,%1,%2,%3};"
        : "+f"(c[0]), "+f"(c[1]), "+f"(c[2]), "+f"(c[3])
        : "r"(a[0]), "r"(a[1]), "r"(a[2]), "r"(a[3]), "r"(b[0]), "r"(b[1]));
}

__device__ __forceinline__ void cp16(uint32_t s, const void* g) {
    asm volatile("cp.async.cg.shared.global [%0], [%1], 16;" :: "r"(s), "l"(g));
}
__device__ __forceinline__ void cp_commit() { asm volatile("cp.async.commit_group;"); }
__device__ __forceinline__ void cp_wait0()  { asm volatile("cp.async.wait_group 0;"); }

// ---------------------------------------------------------------------------
// NT TF32 tensor-core GEMM: C[M,N] = alpha * A[M,K] @ B[N,K]^T (+ bias)
// BM=BN=128, BK=16, 256 threads (8 warps: 2 m x 4 n), warp tile 64x32,
// mma m16n8k8 grid 4x4 per warp. cp.async double buffer.
// biasMode: 0 = none, 1 = bias[n] (per column), 2 = bias[m] (per row)
// Batched over blockIdx.z (B uses z / bzdiv).
// Requires M%128==0, N%128==0, K%16==0 (true for every call here).
// ---------------------------------------------------------------------------
#define BM 128
#define BN 128
#define BKT 16
#define STR 20   // smem row stride (floats); (20*gid+tig)%32 bijective on warp

__global__ __launch_bounds__(256, 2) void gemm_nt_tf32(
    const float* __restrict__ A, int lda, long strideA,
    const float* __restrict__ B, int ldb, long strideB, int bzdiv,
    const float* __restrict__ bias, int biasMode,
    float* __restrict__ C, int ldc, long strideC,
    int M, int N, int K, float alpha)
{
    __shared__ float As[2][BM * STR];
    __shared__ float Bs[2][BN * STR];

    const int tid = threadIdx.x;
    const int bz  = blockIdx.z;
    A += (size_t)bz * strideA;
    B += (size_t)(bz / bzdiv) * strideB;
    C += (size_t)bz * strideC;

    const int bm = blockIdx.y * BM;
    const int bn = blockIdx.x * BN;

    const int warp = tid >> 5;
    const int lane = tid & 31;
    const int gid  = lane >> 2;   // 0..7
    const int tig  = lane & 3;    // 0..3
    const int wy = warp >> 2;     // 0..1 -> m
    const int wx = warp & 3;      // 0..3 -> n
    const int wm = wy * 64;
    const int wn = wx * 32;

    // staging indices: tile 128 rows x 16 cols = 512 float4; 2 per thread per matrix
    const int sr = tid >> 2;        // 0..63
    const int sc = (tid & 3) * 4;   // 0,4,8,12

    const float* Ag0 = A + (size_t)(bm + sr)      * lda + sc;
    const float* Ag1 = A + (size_t)(bm + sr + 64) * lda + sc;
    const float* Bg0 = B + (size_t)(bn + sr)      * ldb + sc;
    const float* Bg1 = B + (size_t)(bn + sr + 64) * ldb + sc;

    const uint32_t sA = (uint32_t)__cvta_generic_to_shared(&As[0][0]);
    const uint32_t sB = (uint32_t)__cvta_generic_to_shared(&Bs[0][0]);
    const uint32_t bufBytes = BM * STR * 4;
    const uint32_t offA0 = (sr * STR + sc) * 4;
    const uint32_t offA1 = ((sr + 64) * STR + sc) * 4;

    float acc[4][4][4];
    #pragma unroll
    for (int i = 0; i < 4; i++)
        #pragma unroll
        for (int j = 0; j < 4; j++)
            #pragma unroll
            for (int r = 0; r < 4; r++) acc[i][j][r] = 0.f;

    const int T = K / BKT;

    // stage tile 0 -> buf 0
    cp16(sA + offA0, Ag0); cp16(sA + offA1, Ag1);
    cp16(sB + offA0, Bg0); cp16(sB + offA1, Bg1);
    cp_commit();

    int buf = 0;
    for (int t = 0; t < T; t++) {
        cp_wait0();
        __syncthreads();
        if (t + 1 < T) {
            const int k0 = (t + 1) * BKT;
            const uint32_t db = (buf ^ 1) * bufBytes;
            cp16(sA + db + offA0, Ag0 + k0); cp16(sA + db + offA1, Ag1 + k0);
            cp16(sB + db + offA0, Bg0 + k0); cp16(sB + db + offA1, Bg1 + k0);
            cp_commit();
        }

        const float* Ab = &As[buf][0];
        const float* Bb = &Bs[buf][0];
        #pragma unroll
        for (int ks = 0; ks < 2; ks++) {
            const int kb = ks * 8;
            uint32_t af[4][4], bf[4][2];
            #pragma unroll
            for (int mt = 0; mt < 4; mt++) {
                const float* p = Ab + (wm + mt * 16) * STR + kb;
                af[mt][0] = f2t(p[(gid    ) * STR + tig    ]);
                af[mt][1] = f2t(p[(gid + 8) * STR + tig    ]);
                af[mt][2] = f2t(p[(gid    ) * STR + tig + 4]);
                af[mt][3] = f2t(p[(gid + 8) * STR + tig + 4]);
            }
            #pragma unroll
            for (int nt = 0; nt < 4; nt++) {
                const float* p = Bb + (wn + nt * 8) * STR + kb;
                bf[nt][0] = f2t(p[gid * STR + tig    ]);
                bf[nt][1] = f2t(p[gid * STR + tig + 4]);
            }
            #pragma unroll
            for (int mt = 0; mt < 4; mt++)
                #pragma unroll
                for (int nt = 0; nt < 4; nt++)
                    mma_tf32(acc[mt][nt], af[mt], bf[nt]);
        }
        buf ^= 1;
    }

    // Epilogue
    #pragma unroll
    for (int mt = 0; mt < 4; mt++) {
        const int row = bm + wm + mt * 16 + gid;
        #pragma unroll
        for (int nt = 0; nt < 4; nt++) {
            const int col = bn + wn + nt * 8 + 2 * tig;
            float bc0 = 0.f, bc1 = 0.f, br0 = 0.f, br8 = 0.f;
            if (biasMode == 1) { bc0 = bias[col]; bc1 = bias[col + 1]; }
            else if (biasMode == 2) { br0 = bias[row]; br8 = bias[row + 8]; }
            float2 v01, v23;
            v01.x = alpha * acc[mt][nt][0] + bc0 + br0;
            v01.y = alpha * acc[mt][nt][1] + bc1 + br0;
            v23.x = alpha * acc[mt][nt][2] + bc0 + br8;
            v23.y = alpha * acc[mt][nt][3] + bc1 + br8;
            *(float2*)(C + (size_t)row * ldc + col)       = v01;
            *(float2*)(C + (size_t)(row + 8) * ldc + col) = v23;
        }
    }
}

// ---------------------------------------------------------------------------
// RoPE in place: t is [seq, nheads*128]; pair (d, d+64) rotated by pos*inv_freq[d]
// inv_freq = 10000^(-2d/128) = exp2f(-d * (2*log2(10000)/128))
// ---------------------------------------------------------------------------
__global__ void rope_kernel(float* __restrict__ t,
                            const int* __restrict__ pos_ids,
                            int nheads)
{
    int idx = blockIdx.x * blockDim.x + threadIdx.x;
    int total = SEQ * nheads * 64;
    if (idx >= total) return;
    int d = idx & 63;
    int h = (idx >> 6) % nheads;
    int srow = idx / (64 * nheads);

    float pos = (float)pos_ids[srow];
    // 2*log2(10000)/128 = log2(10000)/64
    const float LOG2_10000_OVER_64 = 0.20762050594046405f;
    float inv = exp2f(-(float)d * LOG2_10000_OVER_64);
    float ang = pos * inv;
    float c, sn;
    __sincosf(ang, &sn, &c);

    float* p = t + (size_t)srow * (nheads * HD) + h * HD;
    float lo = p[d], hi = p[d + 64];
    p[d]      = lo * c - hi * sn;
    p[d + 64] = hi * c + lo * sn;
}

// ---------------------------------------------------------------------------
// Row softmax over S: one block (256 thr) per row of 2048
// ---------------------------------------------------------------------------
__global__ __launch_bounds__(256) void softmax_kernel(float* __restrict__ S)
{
    const int n = SEQ;
    float* row = S + (size_t)blockIdx.x * n;
    int tid = threadIdx.x;
    int wid = tid >> 5, lid = tid & 31;
    __shared__ float red[8];

    float v[8];
    float m = -1e30f;
    #pragma unroll
    for (int i = 0; i < 8; i++) { v[i] = row[tid + i * 256]; m = fmaxf(m, v[i]); }
    #pragma unroll
    for (int o = 16; o; o >>= 1) m = fmaxf(m, __shfl_xor_sync(0xffffffffu, m, o));
    if (lid == 0) red[wid] = m;
    __syncthreads();
    float bm = red[0];
    #pragma unroll
    for (int i = 1; i < 8; i++) bm = fmaxf(bm, red[i]);
    __syncthreads();

    float sum = 0.f;
    #pragma unroll
    for (int i = 0; i < 8; i++) { v[i] = __expf(v[i] - bm); sum += v[i]; }
    #pragma unroll
    for (int o = 16; o; o >>= 1) sum += __shfl_xor_sync(0xffffffffu, sum, o);
    if (lid == 0) red[wid] = sum;
    __syncthreads();
    float tot = 0.f;
    #pragma unroll
    for (int i = 0; i < 8; i++) tot += red[i];
    float inv = 1.0f / tot;
    #pragma unroll
    for (int i = 0; i < 8; i++) row[tid + i * 256] = v[i] * inv;
}

// ---------------------------------------------------------------------------
// Launch
// inputs: 0:x 1:position_ids 2:wq 3:bq 4:wk 5:bk 6:wv 7:bv 8:wo 9:bo
// ---------------------------------------------------------------------------
extern "C" void kernel_launch(void* const* d_in, const int* in_sizes, int n_in,
                              void* d_out, int out_size)
{
    const float* x   = (const float*)d_in[0];
    const int*   pid = (const int*)  d_in[1];
    const float* wq  = (const float*)d_in[2];
    const float* bq  = (const float*)d_in[3];
    const float* wk  = (const float*)d_in[4];
    const float* bk  = (const float*)d_in[5];
    const float* wv  = (const float*)d_in[6];
    const float* bv  = (const float*)d_in[7];
    const float* wo  = (const float*)d_in[8];
    const float* bo  = (const float*)d_in[9];
    float* out = (float*)d_out;

    float *q, *k, *vt, *s, *attn;
    cudaGetSymbolAddress((void**)&q,    g_q);
    cudaGetSymbolAddress((void**)&k,    g_k);
    cudaGetSymbolAddress((void**)&vt,   g_vt);
    cudaGetSymbolAddress((void**)&s,    g_s);
    cudaGetSymbolAddress((void**)&attn, g_attn);

    dim3 thr(256);

    // 1. Q/K projections (NT):  q = x @ wq^T + bq ; k = x @ wk^T + bk
    gemm_nt_tf32<<<dim3(QDIM / 128, SEQ / 128, 1), thr>>>(
        x, HIDDEN, 0, wq, HIDDEN, 0, 1, bq, 1, q, QDIM, 0, SEQ, QDIM, HIDDEN, 1.0f);
    gemm_nt_tf32<<<dim3(KVDIM / 128, SEQ / 128, 1), thr>>>(
        x, HIDDEN, 0, wk, HIDDEN, 0, 1, bk, 1, k, KVDIM, 0, SEQ, KVDIM, HIDDEN, 1.0f);

    // 2. V projection, TRANSPOSED: vt[n][s] = sum_h wv[n][h] * x[s][h] + bv[n]
    //    (NT with A = wv, B = x; bias is per ROW of C)
    gemm_nt_tf32<<<dim3(SEQ / 128, KVDIM / 128, 1), thr>>>(
        wv, HIDDEN, 0, x, HIDDEN, 0, 1, bv, 2, vt, SEQ, 0, KVDIM, SEQ, HIDDEN, 1.0f);

    // 3. RoPE on q (32 heads) and k (8 heads)
    {
        int tq = SEQ * NH  * 64;
        int tk = SEQ * NKV * 64;
        rope_kernel<<<(tq + 255) / 256, 256>>>(q, pid, NH);
        rope_kernel<<<(tk + 255) / 256, 256>>>(k, pid, NKV);
    }

    // 4. Scores: S[h] = (Q_h @ K_{h/4}^T) / sqrt(128)  (batched over 32 heads)
    const float inv_sqrt_d = 0.08838834764831845f;
    gemm_nt_tf32<<<dim3(SEQ / 128, SEQ / 128, NH), thr>>>(
        q, QDIM, HD,
        k, KVDIM, HD, 4,
        nullptr, 0,
        s, SEQ, (long)SEQ * SEQ,
        SEQ, SEQ, HD, inv_sqrt_d);

    // 5. Softmax over each of 32*2048 rows
    softmax_kernel<<<NH * SEQ, 256>>>(s);

    // 6. attn[h] = P_h @ V_{h/4} = P_h @ (vt rows of kv head)^T  (NT, batched)
    gemm_nt_tf32<<<dim3(HD / 128, SEQ / 128, NH), thr>>>(
        s, SEQ, (long)SEQ * SEQ,
        vt, SEQ, (long)HD * SEQ, 4,
        nullptr, 0,
        attn, QDIM, HD,
        SEQ, HD, SEQ, 1.0f);

    // 7. Output projection: out = attn @ wo^T + bo  (NT)
    gemm_nt_tf32<<<dim3(HIDDEN / 128, SEQ / 128, 1), thr>>>(
        attn, QDIM, 0, wo, QDIM, 0, 1, bo, 1, out, HIDDEN, 0, SEQ, HIDDEN, QDIM, 1.0f);
}